// round 10
// baseline (speedup 1.0000x reference)
#include <cuda_runtime.h>
#include <cuda_fp16.h>
#include <math.h>
#include <stdint.h>

// ---------------- problem-size constants ----------------
static constexpr int NMAX = 131072;   // nodes
static constexpr int EMAX = 1048576;  // edges (excl. self loops)

// ---------------- scratch (device globals, no allocs) ----------------
__device__ __half g_x[(size_t)NMAX * 256];   // layer activations (fp16)
__device__ __half g_h[(size_t)NMAX * 256];   // post-GEMM per-head features (fp16)
__device__ __half g_w[98304];                // fp16 weights: W1 | W2 | W3
__device__ float  g_as[NMAX * 4];            // alpha_src per node/head
__device__ float  g_ad[NMAX * 4];            // alpha_dst per node/head
__device__ int    g_cnt[NMAX];               // histogram, then scatter cursor
__device__ int    g_rp[NMAX + 1];            // CSR row pointers (by dst)
__device__ int    g_part[256];               // scan partials
__device__ int    g_csrc[EMAX + NMAX];       // src node per CSR slot (self loop in slot 0)

static constexpr int WOFF1 = 0;         // 64*256
static constexpr int WOFF2 = 16384;     // 256*256
static constexpr int WOFF3 = 81920;     // 256*64

// ---------------- weight fp32 -> fp16 pre-convert ----------------
__global__ void k_wcvt(const float* __restrict__ W1, const float* __restrict__ W2,
                       const float* __restrict__ W3) {
    int t = blockIdx.x * blockDim.x + threadIdx.x;  // 0..98303
    float v;
    if (t < 16384) v = W1[t];
    else if (t < 81920) v = W2[t - 16384];
    else v = W3[t - 81920];
    g_w[t] = __float2half_rn(v);
}

// ---------------- CSR build ----------------
__global__ void k_fill1(int n) {
    int t = blockIdx.x * blockDim.x + threadIdx.x;
    if (t < n) g_cnt[t] = 1;  // self loop
}

__global__ void k_count(const int* __restrict__ ei, int E) {
    int t = blockIdx.x * blockDim.x + threadIdx.x;
    if (t < E) atomicAdd(&g_cnt[ei[E + t]], 1);
}

__global__ void k_scan1(int n) {
    __shared__ int sm[1024];
    int t = threadIdx.x;
    int g = blockIdx.x * 1024 + t;
    int v = (g < n) ? g_cnt[g] : 0;
    sm[t] = v;
    __syncthreads();
    for (int off = 1; off < 1024; off <<= 1) {
        int add = (t >= off) ? sm[t - off] : 0;
        __syncthreads();
        sm[t] += add;
        __syncthreads();
    }
    if (g < n) g_rp[g] = sm[t] - v;  // exclusive within block
    if (t == 1023) g_part[blockIdx.x] = sm[t];
}

__global__ void k_scan2(int nblocks) {
    __shared__ int sm[256];
    int t = threadIdx.x;
    int v = (t < nblocks) ? g_part[t] : 0;
    sm[t] = v;
    __syncthreads();
    for (int off = 1; off < 256; off <<= 1) {
        int add = (t >= off) ? sm[t - off] : 0;
        __syncthreads();
        sm[t] += add;
        __syncthreads();
    }
    if (t < nblocks) g_part[t] = sm[t] - v;  // exclusive block offsets
}

// scan finalize + self-loop placement + cursor init (merged)
__global__ void k_scan3s(int n, int etot) {
    int t = blockIdx.x * blockDim.x + threadIdx.x;
    if (t < n) {
        int p = g_rp[t] + g_part[t >> 10];
        g_rp[t] = p;
        g_csrc[p] = t;      // self loop in slot 0 of each segment
        g_cnt[t] = p + 1;   // cursor for real edges
    }
    if (t == 0) g_rp[n] = etot;
}

__global__ void k_scatter(const int* __restrict__ ei, int E) {
    int t = blockIdx.x * blockDim.x + threadIdx.x;
    if (t < E) {
        int s = ei[t];
        int d = ei[E + t];
        int pos = atomicAdd(&g_cnt[d], 1);
        g_csrc[pos] = s;
    }
}

// ---------------- fp16 tensor-core GEMM + fused alpha, cp.async 2-stage pipeline ----------------
__device__ __forceinline__ uint32_t s2u(const void* p) {
    return (uint32_t)__cvta_generic_to_shared(p);
}

__device__ __forceinline__ void cpa16(uint32_t dst, const void* src) {
    asm volatile("cp.async.cg.shared.global [%0], [%1], 16;" :: "r"(dst), "l"(src));
}
#define CP_COMMIT asm volatile("cp.async.commit_group;")
#define CP_WAIT1  asm volatile("cp.async.wait_group 1;")
#define CP_WAIT0  asm volatile("cp.async.wait_group 0;")

__device__ __forceinline__ void ldsm_x4(uint32_t* r, uint32_t addr) {
    asm volatile("ldmatrix.sync.aligned.m8n8.x4.shared.b16 {%0,%1,%2,%3}, [%4];"
                 : "=r"(r[0]), "=r"(r[1]), "=r"(r[2]), "=r"(r[3]) : "r"(addr));
}

__device__ __forceinline__ void ldsm_x2t(uint32_t* r, uint32_t addr) {
    asm volatile("ldmatrix.sync.aligned.m8n8.x2.trans.shared.b16 {%0,%1}, [%2];"
                 : "=r"(r[0]), "=r"(r[1]) : "r"(addr));
}

__device__ __forceinline__ void mma_f16(float* d, const uint32_t* a, const uint32_t* b) {
    asm volatile(
        "mma.sync.aligned.m16n8k16.row.col.f32.f16.f16.f32 "
        "{%0,%1,%2,%3}, {%4,%5,%6,%7}, {%8,%9}, {%0,%1,%2,%3};"
        : "+f"(d[0]), "+f"(d[1]), "+f"(d[2]), "+f"(d[3])
        : "r"(a[0]), "r"(a[1]), "r"(a[2]), "r"(a[3]), "r"(b[0]), "r"(b[1]));
}

// BM=128, BN=64(=1 head), BK=32; 8 warps, 32x32 tile each (2x4 m16n8k16).
// A from g_x (fp16) via cp.async, or gathered emb[x[row]] (conv1, sync writes).
// B from g_w (fp16) via cp.async. Double-buffered stages.
template <bool GATHER>
__global__ __launch_bounds__(256) void k_gemm_f16(
    int woff, int K, int NN,
    const int* __restrict__ xidx, const float* __restrict__ emb,
    const float* __restrict__ asrc, const float* __restrict__ adst, int Hstride) {
    __shared__ __half As[2][128][40];   // [m][k], pad->40 (conflict-free LDSM)
    __shared__ __half Bs[2][32][72];    // [k][n], pad->72 (conflict-free LDSM.T)
    __shared__ float sm_s[2][128], sm_d[2][128];

    const __half* Bw = g_w + woff;
    const int t = threadIdx.x;
    const int bm = blockIdx.y * 128;
    const int bn = blockIdx.x * 64;
    const int hh = blockIdx.x;       // head index (BN == head width == 64)
    const int warp = t >> 5, lane = t & 31;
    const int wm = (warp >> 1) * 32;
    const int wn = (warp & 1) * 32;
    const int gid = lane >> 2, tig = lane & 3;
    const int KIT = K >> 5;

    // per-thread load coords
    const int ar0 = t >> 2, ac0 = (t & 3) * 8;            // A chunk 0 (rows 0..63)
    const int ar1 = ar0 + 64;                              // A chunk 1
    const int br = t >> 3, bc = (t & 7) * 8;               // B chunk

    auto load_stage = [&](int it, int buf) {
        int k0 = it * 32;
        if constexpr (GATHER) {
            // conv1: A row = emb[x[row]] (fp32 -> fp16), synchronous smem writes
#pragma unroll
            for (int u = 0; u < 2; u++) {
                int r = (u == 0) ? ar0 : ar1;
                int xi = xidx[bm + r];
                const float* src = emb + xi * 64 + k0 + ac0;
                float4 f0 = *(const float4*)src;
                float4 f1 = *(const float4*)(src + 4);
                __half2* dst = (__half2*)&As[buf][r][ac0];
                dst[0] = __floats2half2_rn(f0.x, f0.y);
                dst[1] = __floats2half2_rn(f0.z, f0.w);
                dst[2] = __floats2half2_rn(f1.x, f1.y);
                dst[3] = __floats2half2_rn(f1.z, f1.w);
            }
        } else {
            cpa16(s2u(&As[buf][ar0][ac0]), &g_x[(size_t)(bm + ar0) * K + k0 + ac0]);
            cpa16(s2u(&As[buf][ar1][ac0]), &g_x[(size_t)(bm + ar1) * K + k0 + ac0]);
        }
        cpa16(s2u(&Bs[buf][br][bc]), &Bw[(size_t)(k0 + br) * NN + bn + bc]);
    };

    float acc[2][4][4];
#pragma unroll
    for (int mi = 0; mi < 2; mi++)
#pragma unroll
        for (int ni = 0; ni < 4; ni++)
#pragma unroll
            for (int r = 0; r < 4; r++) acc[mi][ni][r] = 0.f;

    load_stage(0, 0);
    CP_COMMIT;

    for (int it = 0; it < KIT; it++) {
        const int buf = it & 1;
        if (it + 1 < KIT) {
            load_stage(it + 1, (it + 1) & 1);
            CP_COMMIT;
            CP_WAIT1;
        } else {
            CP_WAIT0;
        }
        __syncthreads();

#pragma unroll
        for (int ks = 0; ks < 32; ks += 16) {
            uint32_t a[2][4], b[4][2];
            int am = ((lane >> 3) & 1) * 8 + (lane & 7);
            int ak = ks + (lane >> 4) * 8;
#pragma unroll
            for (int mi = 0; mi < 2; mi++)
                ldsm_x4(a[mi], s2u(&As[buf][wm + mi * 16 + am][ak]));
#pragma unroll
            for (int ni = 0; ni < 4; ni++)
                ldsm_x2t(b[ni], s2u(&Bs[buf][ks + (lane & 15)][wn + ni * 8]));
#pragma unroll
            for (int mi = 0; mi < 2; mi++)
#pragma unroll
                for (int ni = 0; ni < 4; ni++) mma_f16(acc[mi][ni], a[mi], b[ni]);
        }
        __syncthreads();
    }

    // ---- epilogue 1: store h as fp16 ----
#pragma unroll
    for (int mi = 0; mi < 2; mi++) {
        int row = bm + wm + mi * 16 + gid;
#pragma unroll
        for (int ni = 0; ni < 4; ni++) {
            int col = bn + wn + ni * 8 + tig * 2;
            *(__half2*)&g_h[(size_t)row * NN + col] =
                __floats2half2_rn(acc[mi][ni][0], acc[mi][ni][1]);
            *(__half2*)&g_h[(size_t)(row + 8) * NN + col] =
                __floats2half2_rn(acc[mi][ni][2], acc[mi][ni][3]);
        }
    }

    // ---- epilogue 2: fused alpha_s / alpha_d for head hh ----
    float s_lo[2] = {0.f, 0.f}, s_hi[2] = {0.f, 0.f};
    float d_lo[2] = {0.f, 0.f}, d_hi[2] = {0.f, 0.f};
#pragma unroll
    for (int ni = 0; ni < 4; ni++) {
        int c = wn + ni * 8 + tig * 2;   // col within head (0..63)
        float as0 = asrc[hh * 64 + c], as1 = asrc[hh * 64 + c + 1];
        float ad0 = adst[hh * 64 + c], ad1 = adst[hh * 64 + c + 1];
#pragma unroll
        for (int mi = 0; mi < 2; mi++) {
            s_lo[mi] += acc[mi][ni][0] * as0 + acc[mi][ni][1] * as1;
            s_hi[mi] += acc[mi][ni][2] * as0 + acc[mi][ni][3] * as1;
            d_lo[mi] += acc[mi][ni][0] * ad0 + acc[mi][ni][1] * ad1;
            d_hi[mi] += acc[mi][ni][2] * ad0 + acc[mi][ni][3] * ad1;
        }
    }
#pragma unroll
    for (int off = 1; off <= 2; off <<= 1) {
#pragma unroll
        for (int mi = 0; mi < 2; mi++) {
            s_lo[mi] += __shfl_xor_sync(0xffffffffu, s_lo[mi], off);
            s_hi[mi] += __shfl_xor_sync(0xffffffffu, s_hi[mi], off);
            d_lo[mi] += __shfl_xor_sync(0xffffffffu, d_lo[mi], off);
            d_hi[mi] += __shfl_xor_sync(0xffffffffu, d_hi[mi], off);
        }
    }
    if (tig == 0) {
#pragma unroll
        for (int mi = 0; mi < 2; mi++) {
            int r = wm + mi * 16 + gid;
            sm_s[warp & 1][r] = s_lo[mi];
            sm_s[warp & 1][r + 8] = s_hi[mi];
            sm_d[warp & 1][r] = d_lo[mi];
            sm_d[warp & 1][r + 8] = d_hi[mi];
        }
    }
    __syncthreads();
    if (t < 128) {
        g_as[(size_t)(bm + t) * Hstride + hh] = sm_s[0][t] + sm_s[1][t];
        g_ad[(size_t)(bm + t) * Hstride + hh] = sm_d[0][t] + sm_d[1][t];
    }
}

// ---------------- aggregation (H=4): one warp per destination node ----------------
// Software-pipelined: next edge's src + alpha prefetched during current gather.
__global__ void k_agg4(const float* __restrict__ bias, int n) {
    int warp = (blockIdx.x * blockDim.x + threadIdx.x) >> 5;
    int lane = threadIdx.x & 31;
    if (warp >= n) return;

    const int start = g_rp[warp];
    const int end = g_rp[warp + 1];
    const int myh = lane >> 3;              // 8 lanes per head
    const float adh = g_ad[warp * 4 + myh];

    float acc[8];
#pragma unroll
    for (int k = 0; k < 8; k++) acc[k] = 0.f;
    float denom = 0.f;

    int s = g_csrc[start];                  // self loop always present -> start<end
    float ep = g_as[s * 4 + myh] + adh;

    for (int j = start; j < end; j++) {
        const __half* hp = &g_h[(size_t)s * 256 + lane * 8];
        float e = ep;
        if (j + 1 < end) {
            s = g_csrc[j + 1];
            ep = g_as[s * 4 + myh] + adh;
        }
        uint4 u = *(const uint4*)hp;
        e = e > 0.f ? e : 0.2f * e;
        float w = __expf(e);
        denom += w;
        float2 f0 = __half22float2(*reinterpret_cast<__half2*>(&u.x));
        float2 f1 = __half22float2(*reinterpret_cast<__half2*>(&u.y));
        float2 f2 = __half22float2(*reinterpret_cast<__half2*>(&u.z));
        float2 f3 = __half22float2(*reinterpret_cast<__half2*>(&u.w));
        acc[0] += f0.x * w; acc[1] += f0.y * w;
        acc[2] += f1.x * w; acc[3] += f1.y * w;
        acc[4] += f2.x * w; acc[5] += f2.y * w;
        acc[6] += f3.x * w; acc[7] += f3.y * w;
    }

    float inv = 1.f / (denom + 1e-16f);
    __half2* dst = (__half2*)&g_x[(size_t)warp * 256 + lane * 8];
#pragma unroll
    for (int k = 0; k < 8; k += 2) {
        int c = lane * 8 + k;
        float v0 = acc[k] * inv + bias[c];
        float v1 = acc[k + 1] * inv + bias[c + 1];
        v0 = v0 > 0.f ? v0 : (__expf(v0) - 1.f);
        v1 = v1 > 0.f ? v1 : (__expf(v1) - 1.f);
        dst[k >> 1] = __floats2half2_rn(v0, v1);
    }
}

// ---------------- aggregation (H=1) + fused FC head ----------------
__global__ void k_agg1_fc(const float* __restrict__ bias,
                          const float* __restrict__ fcw, const float* __restrict__ fcb,
                          float* __restrict__ out, int n) {
    int warp = (blockIdx.x * blockDim.x + threadIdx.x) >> 5;
    int lane = threadIdx.x & 31;
    if (warp >= n) return;

    const int start = g_rp[warp];
    const int end = g_rp[warp + 1];
    const float adh = g_ad[warp];

    float a0 = 0.f, a1 = 0.f, denom = 0.f;
    int s = g_csrc[start];
    float ep = g_as[s] + adh;
    for (int j = start; j < end; j++) {
        const __half* hp = &g_h[(size_t)s * 64 + lane * 2];
        float e = ep;
        if (j + 1 < end) {
            s = g_csrc[j + 1];
            ep = g_as[s] + adh;
        }
        float2 f = __half22float2(*(const __half2*)hp);
        e = e > 0.f ? e : 0.2f * e;
        float w = __expf(e);
        denom += w;
        a0 += f.x * w;
        a1 += f.y * w;
    }
    float inv = 1.f / (denom + 1e-16f);
    int c0 = lane * 2, c1 = c0 + 1;
    float v0 = a0 * inv + bias[c0];
    float v1 = a1 * inv + bias[c1];
    v0 = v0 > 0.f ? v0 : (__expf(v0) - 1.f);
    v1 = v1 > 0.f ? v1 : (__expf(v1) - 1.f);

    // FC: out[j] = sum_c v_c * w[c*5+j] + b[j]
#pragma unroll
    for (int j = 0; j < 5; j++) {
        float p = v0 * fcw[c0 * 5 + j] + v1 * fcw[c1 * 5 + j];
#pragma unroll
        for (int off = 16; off; off >>= 1) p += __shfl_xor_sync(0xffffffffu, p, off);
        if (lane == 0) out[warp * 5 + j] = p + fcb[j];
    }
}

// ---------------- launch ----------------
extern "C" void kernel_launch(void* const* d_in, const int* in_sizes, int n_in,
                              void* d_out, int out_size) {
    const int*   x    = (const int*)d_in[0];
    const int*   ei   = (const int*)d_in[1];
    const float* emb  = (const float*)d_in[2];
    const float* W1   = (const float*)d_in[3];
    const float* a1s  = (const float*)d_in[4];
    const float* a1d  = (const float*)d_in[5];
    const float* b1   = (const float*)d_in[6];
    const float* W2   = (const float*)d_in[7];
    const float* a2s  = (const float*)d_in[8];
    const float* a2d  = (const float*)d_in[9];
    const float* b2   = (const float*)d_in[10];
    const float* W3   = (const float*)d_in[11];
    const float* a3s  = (const float*)d_in[12];
    const float* a3d  = (const float*)d_in[13];
    const float* b3   = (const float*)d_in[14];
    const float* fcw  = (const float*)d_in[15];
    const float* fcb  = (const float*)d_in[16];
    float* out = (float*)d_out;

    const int n = in_sizes[0];
    const int E = in_sizes[1] / 2;
    const int etot = E + n;
    const int nb256 = (n + 255) / 256;
    const int eb256 = (E + 255) / 256;
    const int warpGrid = (n * 32) / 256;  // one warp per node, 256-thread blocks
    const int scanBlocks = (n + 1023) / 1024;

    // weights -> fp16 (independent of everything else)
    k_wcvt<<<384, 256>>>(W1, W2, W3);

    // CSR by destination (self loop in slot 0 of each segment)
    k_fill1<<<nb256, 256>>>(n);
    k_count<<<eb256, 256>>>(ei, E);
    k_scan1<<<scanBlocks, 1024>>>(n);
    k_scan2<<<1, 256>>>(scanBlocks);
    k_scan3s<<<nb256, 256>>>(n, etot);
    k_scatter<<<eb256, 256>>>(ei, E);

    // conv1: emb-gather, 64 -> 4x64 concat (alpha fused into GEMM epilogue)
    {
        dim3 grid(4, n / 128);
        k_gemm_f16<true><<<grid, 256>>>(WOFF1, 64, 256, x, emb, a1s, a1d, 4);
        k_agg4<<<warpGrid, 256>>>(b1, n);
    }
    // conv2: 256 -> 4x64 concat
    {
        dim3 grid(4, n / 128);
        k_gemm_f16<false><<<grid, 256>>>(WOFF2, 256, 256, nullptr, nullptr, a2s, a2d, 4);
        k_agg4<<<warpGrid, 256>>>(b2, n);
    }
    // conv3: 256 -> 64 (1 head) + fused FC head
    {
        dim3 grid(1, n / 128);
        k_gemm_f16<false><<<grid, 256>>>(WOFF3, 256, 64, nullptr, nullptr, a3s, a3d, 1);
        k_agg1_fc<<<warpGrid, 256>>>(b3, fcw, fcb, out, n);
    }
}

// round 11
// speedup vs baseline: 1.4980x; 1.4980x over previous
#include <cuda_runtime.h>
#include <cuda_fp16.h>
#include <math.h>
#include <stdint.h>

// ---------------- problem-size constants ----------------
static constexpr int NMAX = 131072;   // nodes
static constexpr int EMAX = 1048576;  // edges (excl. self loops)

// ---------------- scratch (device globals, no allocs) ----------------
__device__ __half g_x[(size_t)NMAX * 256];   // layer activations (fp16)
__device__ __half g_h[(size_t)NMAX * 256];   // post-GEMM per-head features (fp16)
__device__ __half g_w[98304];                // fp16 weights: W1 | W2 | W3
__device__ float  g_as[NMAX * 4];            // alpha_src per node/head
__device__ float  g_ad[NMAX * 4];            // alpha_dst per node/head
__device__ int    g_cnt[NMAX];               // histogram, then scatter cursor
__device__ int    g_rp[NMAX + 1];            // CSR row pointers (by dst)
__device__ int    g_part[256];               // scan partials
__device__ int    g_csrc[EMAX + NMAX];       // src node per CSR slot (self loop in slot 0)

static constexpr int WOFF1 = 0;         // 64*256
static constexpr int WOFF2 = 16384;     // 256*256
static constexpr int WOFF3 = 81920;     // 256*64

// ---------------- weight fp32 -> fp16 pre-convert ----------------
__global__ void k_wcvt(const float* __restrict__ W1, const float* __restrict__ W2,
                       const float* __restrict__ W3) {
    int t = blockIdx.x * blockDim.x + threadIdx.x;  // 0..98303
    float v;
    if (t < 16384) v = W1[t];
    else if (t < 81920) v = W2[t - 16384];
    else v = W3[t - 81920];
    g_w[t] = __float2half_rn(v);
}

// ---------------- CSR build ----------------
__global__ void k_fill1(int n) {
    int t = blockIdx.x * blockDim.x + threadIdx.x;
    if (t < n) g_cnt[t] = 1;  // self loop
}

__global__ void k_count(const int* __restrict__ ei, int E) {
    int t = blockIdx.x * blockDim.x + threadIdx.x;
    if (t < E) atomicAdd(&g_cnt[ei[E + t]], 1);
}

__global__ void k_scan1(int n) {
    __shared__ int sm[1024];
    int t = threadIdx.x;
    int g = blockIdx.x * 1024 + t;
    int v = (g < n) ? g_cnt[g] : 0;
    sm[t] = v;
    __syncthreads();
    for (int off = 1; off < 1024; off <<= 1) {
        int add = (t >= off) ? sm[t - off] : 0;
        __syncthreads();
        sm[t] += add;
        __syncthreads();
    }
    if (g < n) g_rp[g] = sm[t] - v;  // exclusive within block
    if (t == 1023) g_part[blockIdx.x] = sm[t];
}

__global__ void k_scan2(int nblocks) {
    __shared__ int sm[256];
    int t = threadIdx.x;
    int v = (t < nblocks) ? g_part[t] : 0;
    sm[t] = v;
    __syncthreads();
    for (int off = 1; off < 256; off <<= 1) {
        int add = (t >= off) ? sm[t - off] : 0;
        __syncthreads();
        sm[t] += add;
        __syncthreads();
    }
    if (t < nblocks) g_part[t] = sm[t] - v;  // exclusive block offsets
}

// scan finalize + self-loop placement + cursor init (merged)
__global__ void k_scan3s(int n, int etot) {
    int t = blockIdx.x * blockDim.x + threadIdx.x;
    if (t < n) {
        int p = g_rp[t] + g_part[t >> 10];
        g_rp[t] = p;
        g_csrc[p] = t;      // self loop in slot 0 of each segment
        g_cnt[t] = p + 1;   // cursor for real edges
    }
    if (t == 0) g_rp[n] = etot;
}

__global__ void k_scatter(const int* __restrict__ ei, int E) {
    int t = blockIdx.x * blockDim.x + threadIdx.x;
    if (t < E) {
        int s = ei[t];
        int d = ei[E + t];
        int pos = atomicAdd(&g_cnt[d], 1);
        g_csrc[pos] = s;
    }
}

// ---------------- fp16 tensor-core GEMM + fused warp-local alpha ----------------
// BM=128, BN=64*NH (NH heads per CTA), BK=32; 8 warps.
// NH=2: warps in 4x2, each warp 32 rows x one full 64-col head.
// NH=1: warps in 8x1, each warp 16 rows x the single 64-col head.
// Sync LDG->STS loads (known-good R8 style), fp16 weights from g_w.
__device__ __forceinline__ uint32_t s2u(const void* p) {
    return (uint32_t)__cvta_generic_to_shared(p);
}

__device__ __forceinline__ void ldsm_x4(uint32_t* r, uint32_t addr) {
    asm volatile("ldmatrix.sync.aligned.m8n8.x4.shared.b16 {%0,%1,%2,%3}, [%4];"
                 : "=r"(r[0]), "=r"(r[1]), "=r"(r[2]), "=r"(r[3]) : "r"(addr));
}

__device__ __forceinline__ void ldsm_x2t(uint32_t* r, uint32_t addr) {
    asm volatile("ldmatrix.sync.aligned.m8n8.x2.trans.shared.b16 {%0,%1}, [%2];"
                 : "=r"(r[0]), "=r"(r[1]) : "r"(addr));
}

__device__ __forceinline__ void mma_f16(float* d, const uint32_t* a, const uint32_t* b) {
    asm volatile(
        "mma.sync.aligned.m16n8k16.row.col.f32.f16.f16.f32 "
        "{%0,%1,%2,%3}, {%4,%5,%6,%7}, {%8,%9}, {%0,%1,%2,%3};"
        : "+f"(d[0]), "+f"(d[1]), "+f"(d[2]), "+f"(d[3])
        : "r"(a[0]), "r"(a[1]), "r"(a[2]), "r"(a[3]), "r"(b[0]), "r"(b[1]));
}

template <bool GATHER, int NH>
__global__ __launch_bounds__(256) void k_gemm_f16(
    int woff, int K, int NN,
    const int* __restrict__ xidx, const float* __restrict__ emb,
    const float* __restrict__ asrc, const float* __restrict__ adst, int Htot) {
    constexpr int BN = 64 * NH;
    constexpr int MI = NH;                 // m16 fragments per warp (2 or 1)
    __shared__ __half As[128][40];         // [m][k], pad->40 halfs (conflict-free LDSM)
    __shared__ __half Bs[32][BN + 8];      // [k][n], pad ==8 mod 32 words (conflict-free LDSM.T)

    const __half* Bw = g_w + woff;
    const int t = threadIdx.x;
    const int bm = blockIdx.y * 128;
    const int bn = blockIdx.x * BN;
    const int warp = t >> 5, lane = t & 31;
    const int wm = (NH == 2) ? (warp >> 1) * 32 : warp * 16;
    const int hw = (NH == 2) ? (warp & 1) : 0;   // head within CTA
    const int hh = blockIdx.x * NH + hw;         // global head index
    const int wn = hw * 64;
    const int gid = lane >> 2, tig = lane & 3;

    float acc[MI][8][4];
#pragma unroll
    for (int mi = 0; mi < MI; mi++)
#pragma unroll
        for (int ni = 0; ni < 8; ni++)
#pragma unroll
            for (int r = 0; r < 4; r++) acc[mi][ni][r] = 0.f;

    for (int k0 = 0; k0 < K; k0 += 32) {
        // ---- A tile: 128 x 32 halfs ----
        if constexpr (GATHER) {
            // conv1: A row = emb[x[row]] (fp32 -> fp16)
#pragma unroll
            for (int u = 0; u < 2; u++) {
                int linear = t + u * 256;
                int r = linear >> 2;
                int c = (linear & 3) * 8;
                int xi = xidx[bm + r];
                const float* src = emb + xi * 64 + k0 + c;
                float4 f0 = *(const float4*)src;
                float4 f1 = *(const float4*)(src + 4);
                __half2* dst = (__half2*)&As[r][c];
                dst[0] = __floats2half2_rn(f0.x, f0.y);
                dst[1] = __floats2half2_rn(f0.z, f0.w);
                dst[2] = __floats2half2_rn(f1.x, f1.y);
                dst[3] = __floats2half2_rn(f1.z, f1.w);
            }
        } else {
#pragma unroll
            for (int u = 0; u < 2; u++) {
                int linear = t + u * 256;
                int r = linear >> 2;
                int c = (linear & 3) * 8;
                *(uint4*)&As[r][c] = *(const uint4*)&g_x[(size_t)(bm + r) * K + k0 + c];
            }
        }
        // ---- B tile: 32 x BN halfs (fp16 weights) ----
#pragma unroll
        for (int u = 0; u < NH; u++) {
            int linear = t + u * 256;
            int r = (NH == 2) ? (linear >> 4) : (linear >> 3);
            int c = (NH == 2) ? ((linear & 15) * 8) : ((linear & 7) * 8);
            *(uint4*)&Bs[r][c] = *(const uint4*)&Bw[(size_t)(k0 + r) * NN + bn + c];
        }
        __syncthreads();

#pragma unroll
        for (int ks = 0; ks < 32; ks += 16) {
            uint32_t a[MI][4], b[8][2];
            int am = ((lane >> 3) & 1) * 8 + (lane & 7);
            int ak = ks + (lane >> 4) * 8;
#pragma unroll
            for (int mi = 0; mi < MI; mi++)
                ldsm_x4(a[mi], s2u(&As[wm + mi * 16 + am][ak]));
#pragma unroll
            for (int ni = 0; ni < 8; ni++)
                ldsm_x2t(b[ni], s2u(&Bs[ks + (lane & 15)][wn + ni * 8]));
#pragma unroll
            for (int mi = 0; mi < MI; mi++)
#pragma unroll
                for (int ni = 0; ni < 8; ni++) mma_f16(acc[mi][ni], a[mi], b[ni]);
        }
        __syncthreads();
    }

    // ---- epilogue 1: store h as fp16 ----
#pragma unroll
    for (int mi = 0; mi < MI; mi++) {
        int row = bm + wm + mi * 16 + gid;
#pragma unroll
        for (int ni = 0; ni < 8; ni++) {
            int col = bn + wn + ni * 8 + tig * 2;
            *(__half2*)&g_h[(size_t)row * NN + col] =
                __floats2half2_rn(acc[mi][ni][0], acc[mi][ni][1]);
            *(__half2*)&g_h[(size_t)(row + 8) * NN + col] =
                __floats2half2_rn(acc[mi][ni][2], acc[mi][ni][3]);
        }
    }

    // ---- epilogue 2: warp-local fused alpha (warp owns full 64-col head) ----
    float s_lo[MI], s_hi[MI], d_lo[MI], d_hi[MI];
#pragma unroll
    for (int mi = 0; mi < MI; mi++) { s_lo[mi] = s_hi[mi] = d_lo[mi] = d_hi[mi] = 0.f; }
#pragma unroll
    for (int ni = 0; ni < 8; ni++) {
        int c = ni * 8 + tig * 2;   // col within head (0..63)
        float as0 = asrc[hh * 64 + c], as1 = asrc[hh * 64 + c + 1];
        float ad0 = adst[hh * 64 + c], ad1 = adst[hh * 64 + c + 1];
#pragma unroll
        for (int mi = 0; mi < MI; mi++) {
            s_lo[mi] += acc[mi][ni][0] * as0 + acc[mi][ni][1] * as1;
            s_hi[mi] += acc[mi][ni][2] * as0 + acc[mi][ni][3] * as1;
            d_lo[mi] += acc[mi][ni][0] * ad0 + acc[mi][ni][1] * ad1;
            d_hi[mi] += acc[mi][ni][2] * ad0 + acc[mi][ni][3] * ad1;
        }
    }
#pragma unroll
    for (int off = 1; off <= 2; off <<= 1) {
#pragma unroll
        for (int mi = 0; mi < MI; mi++) {
            s_lo[mi] += __shfl_xor_sync(0xffffffffu, s_lo[mi], off);
            s_hi[mi] += __shfl_xor_sync(0xffffffffu, s_hi[mi], off);
            d_lo[mi] += __shfl_xor_sync(0xffffffffu, d_lo[mi], off);
            d_hi[mi] += __shfl_xor_sync(0xffffffffu, d_hi[mi], off);
        }
    }
    if (tig == 0) {
#pragma unroll
        for (int mi = 0; mi < MI; mi++) {
            int r0 = bm + wm + mi * 16 + gid;
            g_as[(size_t)r0 * Htot + hh] = s_lo[mi];
            g_ad[(size_t)r0 * Htot + hh] = d_lo[mi];
            g_as[(size_t)(r0 + 8) * Htot + hh] = s_hi[mi];
            g_ad[(size_t)(r0 + 8) * Htot + hh] = d_hi[mi];
        }
    }
}

// ---------------- aggregation (H=4): one warp per destination node (R8 form) ----------------
__global__ void k_agg4(const float* __restrict__ bias, int n) {
    int warp = (blockIdx.x * blockDim.x + threadIdx.x) >> 5;
    int lane = threadIdx.x & 31;
    if (warp >= n) return;

    const int start = g_rp[warp];
    const int end = g_rp[warp + 1];
    const int myh = lane >> 3;              // 8 lanes per head
    const float adh = g_ad[warp * 4 + myh];

    float acc[8];
#pragma unroll
    for (int k = 0; k < 8; k++) acc[k] = 0.f;
    float denom = 0.f;

    for (int j = start; j < end; j++) {
        int s = g_csrc[j];
        float e = g_as[s * 4 + myh] + adh;
        e = e > 0.f ? e : 0.2f * e;
        float w = __expf(e);
        denom += w;
        uint4 u = *(const uint4*)&g_h[(size_t)s * 256 + lane * 8];
        float2 f0 = __half22float2(*reinterpret_cast<__half2*>(&u.x));
        float2 f1 = __half22float2(*reinterpret_cast<__half2*>(&u.y));
        float2 f2 = __half22float2(*reinterpret_cast<__half2*>(&u.z));
        float2 f3 = __half22float2(*reinterpret_cast<__half2*>(&u.w));
        acc[0] += f0.x * w; acc[1] += f0.y * w;
        acc[2] += f1.x * w; acc[3] += f1.y * w;
        acc[4] += f2.x * w; acc[5] += f2.y * w;
        acc[6] += f3.x * w; acc[7] += f3.y * w;
    }

    float inv = 1.f / (denom + 1e-16f);
    __half2* dst = (__half2*)&g_x[(size_t)warp * 256 + lane * 8];
#pragma unroll
    for (int k = 0; k < 8; k += 2) {
        int c = lane * 8 + k;
        float v0 = acc[k] * inv + bias[c];
        float v1 = acc[k + 1] * inv + bias[c + 1];
        v0 = v0 > 0.f ? v0 : (__expf(v0) - 1.f);
        v1 = v1 > 0.f ? v1 : (__expf(v1) - 1.f);
        dst[k >> 1] = __floats2half2_rn(v0, v1);
    }
}

// ---------------- aggregation (H=1) + fused FC head (R8 form) ----------------
__global__ void k_agg1_fc(const float* __restrict__ bias,
                          const float* __restrict__ fcw, const float* __restrict__ fcb,
                          float* __restrict__ out, int n) {
    int warp = (blockIdx.x * blockDim.x + threadIdx.x) >> 5;
    int lane = threadIdx.x & 31;
    if (warp >= n) return;

    const int start = g_rp[warp];
    const int end = g_rp[warp + 1];
    const float adh = g_ad[warp];

    float a0 = 0.f, a1 = 0.f, denom = 0.f;
    for (int j = start; j < end; j++) {
        int s = g_csrc[j];
        float e = g_as[s] + adh;
        e = e > 0.f ? e : 0.2f * e;
        float w = __expf(e);
        denom += w;
        float2 f = __half22float2(*(const __half2*)&g_h[(size_t)s * 64 + lane * 2]);
        a0 += f.x * w;
        a1 += f.y * w;
    }
    float inv = 1.f / (denom + 1e-16f);
    int c0 = lane * 2, c1 = c0 + 1;
    float v0 = a0 * inv + bias[c0];
    float v1 = a1 * inv + bias[c1];
    v0 = v0 > 0.f ? v0 : (__expf(v0) - 1.f);
    v1 = v1 > 0.f ? v1 : (__expf(v1) - 1.f);

    // FC: out[j] = sum_c v_c * w[c*5+j] + b[j]
#pragma unroll
    for (int j = 0; j < 5; j++) {
        float p = v0 * fcw[c0 * 5 + j] + v1 * fcw[c1 * 5 + j];
#pragma unroll
        for (int off = 16; off; off >>= 1) p += __shfl_xor_sync(0xffffffffu, p, off);
        if (lane == 0) out[warp * 5 + j] = p + fcb[j];
    }
}

// ---------------- launch ----------------
extern "C" void kernel_launch(void* const* d_in, const int* in_sizes, int n_in,
                              void* d_out, int out_size) {
    const int*   x    = (const int*)d_in[0];
    const int*   ei   = (const int*)d_in[1];
    const float* emb  = (const float*)d_in[2];
    const float* W1   = (const float*)d_in[3];
    const float* a1s  = (const float*)d_in[4];
    const float* a1d  = (const float*)d_in[5];
    const float* b1   = (const float*)d_in[6];
    const float* W2   = (const float*)d_in[7];
    const float* a2s  = (const float*)d_in[8];
    const float* a2d  = (const float*)d_in[9];
    const float* b2   = (const float*)d_in[10];
    const float* W3   = (const float*)d_in[11];
    const float* a3s  = (const float*)d_in[12];
    const float* a3d  = (const float*)d_in[13];
    const float* b3   = (const float*)d_in[14];
    const float* fcw  = (const float*)d_in[15];
    const float* fcb  = (const float*)d_in[16];
    float* out = (float*)d_out;

    const int n = in_sizes[0];
    const int E = in_sizes[1] / 2;
    const int etot = E + n;
    const int nb256 = (n + 255) / 256;
    const int eb256 = (E + 255) / 256;
    const int warpGrid = (n * 32) / 256;  // one warp per node, 256-thread blocks
    const int scanBlocks = (n + 1023) / 1024;

    // weights -> fp16 (independent of everything else)
    k_wcvt<<<384, 256>>>(W1, W2, W3);

    // CSR by destination (self loop in slot 0 of each segment)
    k_fill1<<<nb256, 256>>>(n);
    k_count<<<eb256, 256>>>(ei, E);
    k_scan1<<<scanBlocks, 1024>>>(n);
    k_scan2<<<1, 256>>>(scanBlocks);
    k_scan3s<<<nb256, 256>>>(n, etot);
    k_scatter<<<eb256, 256>>>(ei, E);

    // conv1: emb-gather, 64 -> 4x64 concat (alpha fused, 2 heads/CTA)
    {
        dim3 grid(2, n / 128);
        k_gemm_f16<true, 2><<<grid, 256>>>(WOFF1, 64, 256, x, emb, a1s, a1d, 4);
        k_agg4<<<warpGrid, 256>>>(b1, n);
    }
    // conv2: 256 -> 4x64 concat
    {
        dim3 grid(2, n / 128);
        k_gemm_f16<false, 2><<<grid, 256>>>(WOFF2, 256, 256, nullptr, nullptr, a2s, a2d, 4);
        k_agg4<<<warpGrid, 256>>>(b2, n);
    }
    // conv3: 256 -> 64 (1 head) + fused FC head
    {
        dim3 grid(1, n / 128);
        k_gemm_f16<false, 1><<<grid, 256>>>(WOFF3, 256, 64, nullptr, nullptr, a3s, a3d, 1);
        k_agg1_fc<<<warpGrid, 256>>>(b3, fcw, fcb, out, n);
    }
}

// round 12
// speedup vs baseline: 1.5106x; 1.0084x over previous
#include <cuda_runtime.h>
#include <cuda_fp16.h>
#include <math.h>
#include <stdint.h>

// ---------------- problem-size constants ----------------
static constexpr int NMAX = 131072;   // nodes
static constexpr int EMAX = 1048576;  // edges (excl. self loops)

// ---------------- scratch (device globals, no allocs) ----------------
__device__ __half g_x[(size_t)NMAX * 256];   // layer activations (fp16)
__device__ __half g_h[(size_t)NMAX * 256];   // post-GEMM per-head features (fp16)
__device__ __half g_w[98304];                // fp16 weights: W1 | W2 | W3
__device__ float  g_as[NMAX * 4];            // alpha_src per node/head
__device__ float  g_ad[NMAX * 4];            // alpha_dst per node/head
__device__ int    g_cnt[NMAX];               // histogram, then scatter cursor
__device__ int    g_rp[NMAX + 1];            // CSR row pointers (by dst)
__device__ int    g_part[256];               // scan partials
__device__ int    g_csrc[EMAX + NMAX];       // src node per CSR slot (self loop in slot 0)

static constexpr int WOFF1 = 0;         // 64*256
static constexpr int WOFF2 = 16384;     // 256*256
static constexpr int WOFF3 = 81920;     // 256*64

// ---------------- weight fp32 -> fp16 pre-convert ----------------
__global__ void k_wcvt(const float* __restrict__ W1, const float* __restrict__ W2,
                       const float* __restrict__ W3) {
    int t = blockIdx.x * blockDim.x + threadIdx.x;  // 0..98303
    float v;
    if (t < 16384) v = W1[t];
    else if (t < 81920) v = W2[t - 16384];
    else v = W3[t - 81920];
    g_w[t] = __float2half_rn(v);
}

// ---------------- CSR build ----------------
__global__ void k_fill1(int n) {
    int t = blockIdx.x * blockDim.x + threadIdx.x;
    if (t < n) g_cnt[t] = 1;  // self loop
}

__global__ void k_count(const int* __restrict__ ei, int E) {
    int t = blockIdx.x * blockDim.x + threadIdx.x;
    if (t < E) atomicAdd(&g_cnt[__ldcs(&ei[E + t])], 1);
}

__global__ void k_scan1(int n) {
    __shared__ int sm[1024];
    int t = threadIdx.x;
    int g = blockIdx.x * 1024 + t;
    int v = (g < n) ? g_cnt[g] : 0;
    sm[t] = v;
    __syncthreads();
    for (int off = 1; off < 1024; off <<= 1) {
        int add = (t >= off) ? sm[t - off] : 0;
        __syncthreads();
        sm[t] += add;
        __syncthreads();
    }
    if (g < n) g_rp[g] = sm[t] - v;  // exclusive within block
    if (t == 1023) g_part[blockIdx.x] = sm[t];
}

__global__ void k_scan2(int nblocks) {
    __shared__ int sm[256];
    int t = threadIdx.x;
    int v = (t < nblocks) ? g_part[t] : 0;
    sm[t] = v;
    __syncthreads();
    for (int off = 1; off < 256; off <<= 1) {
        int add = (t >= off) ? sm[t - off] : 0;
        __syncthreads();
        sm[t] += add;
        __syncthreads();
    }
    if (t < nblocks) g_part[t] = sm[t] - v;  // exclusive block offsets
}

// scan finalize + self-loop placement + cursor init (merged)
__global__ void k_scan3s(int n, int etot) {
    int t = blockIdx.x * blockDim.x + threadIdx.x;
    if (t < n) {
        int p = g_rp[t] + g_part[t >> 10];
        g_rp[t] = p;
        g_csrc[p] = t;      // self loop in slot 0 of each segment
        g_cnt[t] = p + 1;   // cursor for real edges
    }
    if (t == 0) g_rp[n] = etot;
}

__global__ void k_scatter(const int* __restrict__ ei, int E) {
    int t = blockIdx.x * blockDim.x + threadIdx.x;
    if (t < E) {
        int s = __ldcs(&ei[t]);
        int d = __ldcs(&ei[E + t]);
        int pos = atomicAdd(&g_cnt[d], 1);
        g_csrc[pos] = s;
    }
}

// ---------------- fp16 tensor-core GEMM + fused warp-local alpha ----------------
// BM=128, BN=64*NH (NH heads per CTA), BK=32; 8 warps.
__device__ __forceinline__ uint32_t s2u(const void* p) {
    return (uint32_t)__cvta_generic_to_shared(p);
}

__device__ __forceinline__ void ldsm_x4(uint32_t* r, uint32_t addr) {
    asm volatile("ldmatrix.sync.aligned.m8n8.x4.shared.b16 {%0,%1,%2,%3}, [%4];"
                 : "=r"(r[0]), "=r"(r[1]), "=r"(r[2]), "=r"(r[3]) : "r"(addr));
}

__device__ __forceinline__ void ldsm_x2t(uint32_t* r, uint32_t addr) {
    asm volatile("ldmatrix.sync.aligned.m8n8.x2.trans.shared.b16 {%0,%1}, [%2];"
                 : "=r"(r[0]), "=r"(r[1]) : "r"(addr));
}

__device__ __forceinline__ void mma_f16(float* d, const uint32_t* a, const uint32_t* b) {
    asm volatile(
        "mma.sync.aligned.m16n8k16.row.col.f32.f16.f16.f32 "
        "{%0,%1,%2,%3}, {%4,%5,%6,%7}, {%8,%9}, {%0,%1,%2,%3};"
        : "+f"(d[0]), "+f"(d[1]), "+f"(d[2]), "+f"(d[3])
        : "r"(a[0]), "r"(a[1]), "r"(a[2]), "r"(a[3]), "r"(b[0]), "r"(b[1]));
}

template <bool GATHER, int NH>
__global__ __launch_bounds__(256) void k_gemm_f16(
    int woff, int K, int NN,
    const int* __restrict__ xidx, const float* __restrict__ emb,
    const float* __restrict__ asrc, const float* __restrict__ adst, int Htot) {
    constexpr int BN = 64 * NH;
    constexpr int MI = NH;                 // m16 fragments per warp (2 or 1)
    __shared__ __half As[128][40];         // [m][k], pad->40 halfs (conflict-free LDSM)
    __shared__ __half Bs[32][BN + 8];      // [k][n], pad ==8 mod 32 words (conflict-free LDSM.T)

    const __half* Bw = g_w + woff;
    const int t = threadIdx.x;
    const int bm = blockIdx.y * 128;
    const int bn = blockIdx.x * BN;
    const int warp = t >> 5, lane = t & 31;
    const int wm = (NH == 2) ? (warp >> 1) * 32 : warp * 16;
    const int hw = (NH == 2) ? (warp & 1) : 0;   // head within CTA
    const int hh = blockIdx.x * NH + hw;         // global head index
    const int wn = hw * 64;
    const int gid = lane >> 2, tig = lane & 3;

    float acc[MI][8][4];
#pragma unroll
    for (int mi = 0; mi < MI; mi++)
#pragma unroll
        for (int ni = 0; ni < 8; ni++)
#pragma unroll
            for (int r = 0; r < 4; r++) acc[mi][ni][r] = 0.f;

    for (int k0 = 0; k0 < K; k0 += 32) {
        // ---- A tile: 128 x 32 halfs ----
        if constexpr (GATHER) {
            // conv1: A row = emb[x[row]] (fp32 -> fp16)
#pragma unroll
            for (int u = 0; u < 2; u++) {
                int linear = t + u * 256;
                int r = linear >> 2;
                int c = (linear & 3) * 8;
                int xi = xidx[bm + r];
                const float* src = emb + xi * 64 + k0 + c;
                float4 f0 = *(const float4*)src;
                float4 f1 = *(const float4*)(src + 4);
                __half2* dst = (__half2*)&As[r][c];
                dst[0] = __floats2half2_rn(f0.x, f0.y);
                dst[1] = __floats2half2_rn(f0.z, f0.w);
                dst[2] = __floats2half2_rn(f1.x, f1.y);
                dst[3] = __floats2half2_rn(f1.z, f1.w);
            }
        } else {
#pragma unroll
            for (int u = 0; u < 2; u++) {
                int linear = t + u * 256;
                int r = linear >> 2;
                int c = (linear & 3) * 8;
                *(uint4*)&As[r][c] = __ldcs((const uint4*)&g_x[(size_t)(bm + r) * K + k0 + c]);
            }
        }
        // ---- B tile: 32 x BN halfs (fp16 weights) ----
#pragma unroll
        for (int u = 0; u < NH; u++) {
            int linear = t + u * 256;
            int r = (NH == 2) ? (linear >> 4) : (linear >> 3);
            int c = (NH == 2) ? ((linear & 15) * 8) : ((linear & 7) * 8);
            *(uint4*)&Bs[r][c] = *(const uint4*)&Bw[(size_t)(k0 + r) * NN + bn + c];
        }
        __syncthreads();

#pragma unroll
        for (int ks = 0; ks < 32; ks += 16) {
            uint32_t a[MI][4], b[8][2];
            int am = ((lane >> 3) & 1) * 8 + (lane & 7);
            int ak = ks + (lane >> 4) * 8;
#pragma unroll
            for (int mi = 0; mi < MI; mi++)
                ldsm_x4(a[mi], s2u(&As[wm + mi * 16 + am][ak]));
#pragma unroll
            for (int ni = 0; ni < 8; ni++)
                ldsm_x2t(b[ni], s2u(&Bs[ks + (lane & 15)][wn + ni * 8]));
#pragma unroll
            for (int mi = 0; mi < MI; mi++)
#pragma unroll
                for (int ni = 0; ni < 8; ni++) mma_f16(acc[mi][ni], a[mi], b[ni]);
        }
        __syncthreads();
    }

    // ---- epilogue 1: store h as fp16 (default cache: agg will reuse from L2) ----
#pragma unroll
    for (int mi = 0; mi < MI; mi++) {
        int row = bm + wm + mi * 16 + gid;
#pragma unroll
        for (int ni = 0; ni < 8; ni++) {
            int col = bn + wn + ni * 8 + tig * 2;
            *(__half2*)&g_h[(size_t)row * NN + col] =
                __floats2half2_rn(acc[mi][ni][0], acc[mi][ni][1]);
            *(__half2*)&g_h[(size_t)(row + 8) * NN + col] =
                __floats2half2_rn(acc[mi][ni][2], acc[mi][ni][3]);
        }
    }

    // ---- epilogue 2: warp-local fused alpha (warp owns full 64-col head) ----
    float s_lo[MI], s_hi[MI], d_lo[MI], d_hi[MI];
#pragma unroll
    for (int mi = 0; mi < MI; mi++) { s_lo[mi] = s_hi[mi] = d_lo[mi] = d_hi[mi] = 0.f; }
#pragma unroll
    for (int ni = 0; ni < 8; ni++) {
        int c = ni * 8 + tig * 2;   // col within head (0..63)
        float as0 = asrc[hh * 64 + c], as1 = asrc[hh * 64 + c + 1];
        float ad0 = adst[hh * 64 + c], ad1 = adst[hh * 64 + c + 1];
#pragma unroll
        for (int mi = 0; mi < MI; mi++) {
            s_lo[mi] += acc[mi][ni][0] * as0 + acc[mi][ni][1] * as1;
            s_hi[mi] += acc[mi][ni][2] * as0 + acc[mi][ni][3] * as1;
            d_lo[mi] += acc[mi][ni][0] * ad0 + acc[mi][ni][1] * ad1;
            d_hi[mi] += acc[mi][ni][2] * ad0 + acc[mi][ni][3] * ad1;
        }
    }
#pragma unroll
    for (int off = 1; off <= 2; off <<= 1) {
#pragma unroll
        for (int mi = 0; mi < MI; mi++) {
            s_lo[mi] += __shfl_xor_sync(0xffffffffu, s_lo[mi], off);
            s_hi[mi] += __shfl_xor_sync(0xffffffffu, s_hi[mi], off);
            d_lo[mi] += __shfl_xor_sync(0xffffffffu, d_lo[mi], off);
            d_hi[mi] += __shfl_xor_sync(0xffffffffu, d_hi[mi], off);
        }
    }
    if (tig == 0) {
#pragma unroll
        for (int mi = 0; mi < MI; mi++) {
            int r0 = bm + wm + mi * 16 + gid;
            g_as[(size_t)r0 * Htot + hh] = s_lo[mi];
            g_ad[(size_t)r0 * Htot + hh] = d_lo[mi];
            g_as[(size_t)(r0 + 8) * Htot + hh] = s_hi[mi];
            g_ad[(size_t)(r0 + 8) * Htot + hh] = d_hi[mi];
        }
    }
}

// ---------------- aggregation (H=4): one warp per destination node ----------------
// 2x unrolled with batched independent loads (MLP), streaming hints on csrc + output.
__device__ __forceinline__ void acc8(float* acc, uint4 u, float w) {
    float2 f0 = __half22float2(*reinterpret_cast<__half2*>(&u.x));
    float2 f1 = __half22float2(*reinterpret_cast<__half2*>(&u.y));
    float2 f2 = __half22float2(*reinterpret_cast<__half2*>(&u.z));
    float2 f3 = __half22float2(*reinterpret_cast<__half2*>(&u.w));
    acc[0] += f0.x * w; acc[1] += f0.y * w;
    acc[2] += f1.x * w; acc[3] += f1.y * w;
    acc[4] += f2.x * w; acc[5] += f2.y * w;
    acc[6] += f3.x * w; acc[7] += f3.y * w;
}

__global__ void k_agg4(const float* __restrict__ bias, int n) {
    int warp = (blockIdx.x * blockDim.x + threadIdx.x) >> 5;
    int lane = threadIdx.x & 31;
    if (warp >= n) return;

    const int start = g_rp[warp];
    const int end = g_rp[warp + 1];
    const int myh = lane >> 3;              // 8 lanes per head
    const float adh = g_ad[warp * 4 + myh];

    float acc[8];
#pragma unroll
    for (int k = 0; k < 8; k++) acc[k] = 0.f;
    float denom = 0.f;

    int j = start;
    for (; j + 1 < end; j += 2) {
        int s0 = __ldcs(&g_csrc[j]);
        int s1 = __ldcs(&g_csrc[j + 1]);
        float e0 = g_as[s0 * 4 + myh] + adh;
        float e1 = g_as[s1 * 4 + myh] + adh;
        uint4 u0 = *(const uint4*)&g_h[(size_t)s0 * 256 + lane * 8];
        uint4 u1 = *(const uint4*)&g_h[(size_t)s1 * 256 + lane * 8];
        e0 = e0 > 0.f ? e0 : 0.2f * e0;
        e1 = e1 > 0.f ? e1 : 0.2f * e1;
        float w0 = __expf(e0);
        float w1 = __expf(e1);
        denom += w0 + w1;
        acc8(acc, u0, w0);
        acc8(acc, u1, w1);
    }
    if (j < end) {
        int s = __ldcs(&g_csrc[j]);
        float e = g_as[s * 4 + myh] + adh;
        uint4 u = *(const uint4*)&g_h[(size_t)s * 256 + lane * 8];
        e = e > 0.f ? e : 0.2f * e;
        float w = __expf(e);
        denom += w;
        acc8(acc, u, w);
    }

    float inv = 1.f / (denom + 1e-16f);
    uint4 outv;
    uint32_t* ov = (uint32_t*)&outv;
#pragma unroll
    for (int k = 0; k < 8; k += 2) {
        int c = lane * 8 + k;
        float v0 = acc[k] * inv + bias[c];
        float v1 = acc[k + 1] * inv + bias[c + 1];
        v0 = v0 > 0.f ? v0 : (__expf(v0) - 1.f);
        v1 = v1 > 0.f ? v1 : (__expf(v1) - 1.f);
        __half2 hp = __floats2half2_rn(v0, v1);
        ov[k >> 1] = *reinterpret_cast<uint32_t*>(&hp);
    }
    __stcs((uint4*)&g_x[(size_t)warp * 256 + lane * 8], outv);  // evict-first: keep g_h resident
}

// ---------------- aggregation (H=1) + fused FC head ----------------
__global__ void k_agg1_fc(const float* __restrict__ bias,
                          const float* __restrict__ fcw, const float* __restrict__ fcb,
                          float* __restrict__ out, int n) {
    int warp = (blockIdx.x * blockDim.x + threadIdx.x) >> 5;
    int lane = threadIdx.x & 31;
    if (warp >= n) return;

    const int start = g_rp[warp];
    const int end = g_rp[warp + 1];
    const float adh = g_ad[warp];

    float a0 = 0.f, a1 = 0.f, denom = 0.f;
    int j = start;
    for (; j + 1 < end; j += 2) {
        int s0 = __ldcs(&g_csrc[j]);
        int s1 = __ldcs(&g_csrc[j + 1]);
        float e0 = g_as[s0] + adh;
        float e1 = g_as[s1] + adh;
        float2 f0 = __half22float2(*(const __half2*)&g_h[(size_t)s0 * 64 + lane * 2]);
        float2 f1 = __half22float2(*(const __half2*)&g_h[(size_t)s1 * 64 + lane * 2]);
        e0 = e0 > 0.f ? e0 : 0.2f * e0;
        e1 = e1 > 0.f ? e1 : 0.2f * e1;
        float w0 = __expf(e0);
        float w1 = __expf(e1);
        denom += w0 + w1;
        a0 += f0.x * w0 + f1.x * w1;
        a1 += f0.y * w0 + f1.y * w1;
    }
    if (j < end) {
        int s = __ldcs(&g_csrc[j]);
        float e = g_as[s] + adh;
        float2 f = __half22float2(*(const __half2*)&g_h[(size_t)s * 64 + lane * 2]);
        e = e > 0.f ? e : 0.2f * e;
        float w = __expf(e);
        denom += w;
        a0 += f.x * w;
        a1 += f.y * w;
    }
    float inv = 1.f / (denom + 1e-16f);
    int c0 = lane * 2, c1 = c0 + 1;
    float v0 = a0 * inv + bias[c0];
    float v1 = a1 * inv + bias[c1];
    v0 = v0 > 0.f ? v0 : (__expf(v0) - 1.f);
    v1 = v1 > 0.f ? v1 : (__expf(v1) - 1.f);

    // FC: out[j] = sum_c v_c * w[c*5+j] + b[j]
#pragma unroll
    for (int jj = 0; jj < 5; jj++) {
        float p = v0 * fcw[c0 * 5 + jj] + v1 * fcw[c1 * 5 + jj];
#pragma unroll
        for (int off = 16; off; off >>= 1) p += __shfl_xor_sync(0xffffffffu, p, off);
        if (lane == 0) __stcs(&out[warp * 5 + jj], p + fcb[jj]);
    }
}

// ---------------- launch ----------------
extern "C" void kernel_launch(void* const* d_in, const int* in_sizes, int n_in,
                              void* d_out, int out_size) {
    const int*   x    = (const int*)d_in[0];
    const int*   ei   = (const int*)d_in[1];
    const float* emb  = (const float*)d_in[2];
    const float* W1   = (const float*)d_in[3];
    const float* a1s  = (const float*)d_in[4];
    const float* a1d  = (const float*)d_in[5];
    const float* b1   = (const float*)d_in[6];
    const float* W2   = (const float*)d_in[7];
    const float* a2s  = (const float*)d_in[8];
    const float* a2d  = (const float*)d_in[9];
    const float* b2   = (const float*)d_in[10];
    const float* W3   = (const float*)d_in[11];
    const float* a3s  = (const float*)d_in[12];
    const float* a3d  = (const float*)d_in[13];
    const float* b3   = (const float*)d_in[14];
    const float* fcw  = (const float*)d_in[15];
    const float* fcb  = (const float*)d_in[16];
    float* out = (float*)d_out;

    const int n = in_sizes[0];
    const int E = in_sizes[1] / 2;
    const int etot = E + n;
    const int nb256 = (n + 255) / 256;
    const int eb256 = (E + 255) / 256;
    const int warpGrid = (n * 32) / 256;  // one warp per node, 256-thread blocks
    const int scanBlocks = (n + 1023) / 1024;

    // weights -> fp16 (independent of everything else)
    k_wcvt<<<384, 256>>>(W1, W2, W3);

    // CSR by destination (self loop in slot 0 of each segment)
    k_fill1<<<nb256, 256>>>(n);
    k_count<<<eb256, 256>>>(ei, E);
    k_scan1<<<scanBlocks, 1024>>>(n);
    k_scan2<<<1, 256>>>(scanBlocks);
    k_scan3s<<<nb256, 256>>>(n, etot);
    k_scatter<<<eb256, 256>>>(ei, E);

    // conv1: emb-gather, 64 -> 4x64 concat (alpha fused, 2 heads/CTA)
    {
        dim3 grid(2, n / 128);
        k_gemm_f16<true, 2><<<grid, 256>>>(WOFF1, 64, 256, x, emb, a1s, a1d, 4);
        k_agg4<<<warpGrid, 256>>>(b1, n);
    }
    // conv2: 256 -> 4x64 concat
    {
        dim3 grid(2, n / 128);
        k_gemm_f16<false, 2><<<grid, 256>>>(WOFF2, 256, 256, nullptr, nullptr, a2s, a2d, 4);
        k_agg4<<<warpGrid, 256>>>(b2, n);
    }
    // conv3: 256 -> 64 (1 head) + fused FC head
    {
        dim3 grid(1, n / 128);
        k_gemm_f16<false, 1><<<grid, 256>>>(WOFF3, 256, 64, nullptr, nullptr, a3s, a3d, 1);
        k_agg1_fc<<<warpGrid, 256>>>(b3, fcw, fcb, out, n);
    }
}